// round 3
// baseline (speedup 1.0000x reference)
#include <cuda_runtime.h>
#include <cstdint>

#define PN 16384      // pixels per image (128*128)
#define NIMG 4

// ---------------- scratch (static device arrays; no allocs allowed) ----------
__device__ float g_pre[4 * 512 * 16384];   // pre-GN buffer (conv outputs)
__device__ float g_cat[4 * 640 * 16384];   // [xd | branch d1,d4,d8,d12]
__device__ float g_y2 [4 * 128 * 16384];   // GN2 output
__device__ float g_part[4 * 32 * 8 * 2];   // GN partial sums (n, group, split) x {s,q}

__constant__ int c_rdils[4] = {12, 8, 4, 1};   // slowest-first schedule

// ---------------------------------------------------------------------------
// tf32 tensor-core SGEMM (unchanged from R2): Y[n][m][p] = sum_k A[m][k]*X[n][k][p]
// ---------------------------------------------------------------------------
#define AS_STR 20
#define BS_STR 136
#define AS_SZ  (128 * AS_STR)
#define BS_SZ  (16 * BS_STR)

#define CP16(dst_u32, src_ptr) \
    asm volatile("cp.async.cg.shared.global [%0], [%1], 16;\n" :: "r"(dst_u32), "l"(src_ptr))

#define MMA_TF32(c, a, b)                                                      \
    asm volatile(                                                              \
        "mma.sync.aligned.m16n8k8.row.col.f32.tf32.tf32.f32 "                  \
        "{%0,%1,%2,%3}, {%4,%5,%6,%7}, {%8,%9}, {%0,%1,%2,%3};"                \
        : "+f"((c)[0]), "+f"((c)[1]), "+f"((c)[2]), "+f"((c)[3])               \
        : "r"((a)[0]), "r"((a)[1]), "r"((a)[2]), "r"((a)[3]),                  \
          "r"((b)[0]), "r"((b)[1]))

__global__ void __launch_bounds__(256, 2) gemm_tf32_kernel(
    const float* __restrict__ A, const float* __restrict__ X,
    float* __restrict__ Y, int M, int K)
{
    __shared__ float As[2][AS_SZ];
    __shared__ float Bs[2][BS_SZ];

    const int t  = threadIdx.x;
    const int n  = blockIdx.z;
    const int p0 = blockIdx.x * 128;
    const int m0 = blockIdx.y * 128;

    const float* Xn = X + (size_t)n * K * PN;
    float*       Yn = Y + (size_t)n * M * PN;

    const int warp = t >> 5, lane = t & 31;
    const int wm = warp & 1, wn = warp >> 1;
    const int g  = lane >> 2, tg = lane & 3;

    const uint32_t as_base = (uint32_t)__cvta_generic_to_shared(&As[0][0]);
    const uint32_t bs_base = (uint32_t)__cvta_generic_to_shared(&Bs[0][0]);

    float acc[4][4][4];
#pragma unroll
    for (int i = 0; i < 4; i++)
#pragma unroll
        for (int j = 0; j < 4; j++)
#pragma unroll
            for (int r = 0; r < 4; r++) acc[i][j][r] = 0.f;

    const int nk = K >> 4;

    auto issue_stage = [&](int bufi, int k0) {
#pragma unroll
        for (int i = 0; i < 2; i++) {
            int c   = t + i * 256;
            int row = c >> 2;
            int kc  = (c & 3) * 4;
            uint32_t dst = as_base + (uint32_t)(bufi * AS_SZ + row * AS_STR + kc) * 4u;
            CP16(dst, A + (size_t)(m0 + row) * K + k0 + kc);
        }
#pragma unroll
        for (int i = 0; i < 2; i++) {
            int c   = t + i * 256;
            int row = c >> 5;
            int pc  = (c & 31) * 4;
            uint32_t dst = bs_base + (uint32_t)(bufi * BS_SZ + row * BS_STR + pc) * 4u;
            CP16(dst, Xn + (size_t)(k0 + row) * PN + p0 + pc);
        }
    };

    issue_stage(0, 0);
    asm volatile("cp.async.commit_group;\n" ::: "memory");

    int buf = 0;
    for (int kt = 0; kt < nk; kt++) {
        if (kt + 1 < nk) {
            issue_stage(buf ^ 1, (kt + 1) * 16);
            asm volatile("cp.async.commit_group;\n" ::: "memory");
            asm volatile("cp.async.wait_group 1;\n" ::: "memory");
        } else {
            asm volatile("cp.async.wait_group 0;\n" ::: "memory");
        }
        __syncthreads();

        const float* as = &As[buf][0];
        const float* bs = &Bs[buf][0];
#pragma unroll
        for (int ks = 0; ks < 16; ks += 8) {
            uint32_t af[4][4], bf[4][2];
#pragma unroll
            for (int i = 0; i < 4; i++) {
                int mb = wm * 64 + i * 16;
                af[i][0] = __float_as_uint(as[(mb + g)     * AS_STR + ks + tg]);
                af[i][1] = __float_as_uint(as[(mb + g + 8) * AS_STR + ks + tg]);
                af[i][2] = __float_as_uint(as[(mb + g)     * AS_STR + ks + tg + 4]);
                af[i][3] = __float_as_uint(as[(mb + g + 8) * AS_STR + ks + tg + 4]);
            }
#pragma unroll
            for (int j = 0; j < 4; j++) {
                int nb = wn * 32 + j * 8;
                bf[j][0] = __float_as_uint(bs[(ks + tg)     * BS_STR + nb + g]);
                bf[j][1] = __float_as_uint(bs[(ks + tg + 4) * BS_STR + nb + g]);
            }
#pragma unroll
            for (int i = 0; i < 4; i++)
#pragma unroll
                for (int j = 0; j < 4; j++)
                    MMA_TF32(acc[i][j], af[i], bf[j]);
        }
        __syncthreads();
        buf ^= 1;
    }

#pragma unroll
    for (int i = 0; i < 4; i++) {
        int mrow = m0 + wm * 64 + i * 16 + g;
#pragma unroll
        for (int j = 0; j < 4; j++) {
            int col = p0 + wn * 32 + j * 8 + 2 * tg;
            *(float2*)(Yn + (size_t)mrow * PN + col)       = make_float2(acc[i][j][0], acc[i][j][1]);
            *(float2*)(Yn + (size_t)(mrow + 8) * PN + col) = make_float2(acc[i][j][2], acc[i][j][3]);
        }
    }
}

// ---------------------------------------------------------------------------
// GroupNorm split: stats (partial sums, 8 splits/group) + apply (affine+ReLU).
// ---------------------------------------------------------------------------
__global__ void __launch_bounds__(256) gn_stats_kernel(
    const float* __restrict__ in, int Cin_tot, int cpg)
{
    const int g = blockIdx.x, n = blockIdx.y, spl = blockIdx.z;
    const int len = cpg * PN / 4 / 8;
    const float4* in4 = (const float4*)(in + ((size_t)n * Cin_tot + (size_t)g * cpg) * PN)
                        + (size_t)spl * len;
    float s = 0.f, q = 0.f;
    for (int i = threadIdx.x; i < len; i += 256) {
        float4 v = in4[i];
        s += v.x + v.y + v.z + v.w;
        q += v.x * v.x + v.y * v.y + v.z * v.z + v.w * v.w;
    }
    __shared__ float rs[256], rq[256];
    rs[threadIdx.x] = s; rq[threadIdx.x] = q;
    __syncthreads();
    for (int off = 128; off > 0; off >>= 1) {
        if (threadIdx.x < off) {
            rs[threadIdx.x] += rs[threadIdx.x + off];
            rq[threadIdx.x] += rq[threadIdx.x + off];
        }
        __syncthreads();
    }
    if (threadIdx.x == 0) {
        int idx = ((n * 32 + g) * 8 + spl) * 2;
        g_part[idx] = rs[0];
        g_part[idx + 1] = rq[0];
    }
}

__global__ void __launch_bounds__(256) gn_apply_kernel(
    const float* __restrict__ in, float* __restrict__ out,
    const float* __restrict__ gamma, const float* __restrict__ beta,
    int Cin_tot, int Cout_tot, int cbase_out, int cpg)
{
    const int g = blockIdx.x, n = blockIdx.y, spl = blockIdx.z;
    const int len = cpg * PN / 4 / 8;

    __shared__ float s_mean, s_inv;
    if (threadIdx.x == 0) {
        float s = 0.f, q = 0.f;
        int base = (n * 32 + g) * 8;
#pragma unroll
        for (int i = 0; i < 8; i++) {
            s += g_part[(base + i) * 2];
            q += g_part[(base + i) * 2 + 1];
        }
        float cnt = (float)(cpg * PN);
        float mean = s / cnt;
        float var  = q / cnt - mean * mean;
        s_mean = mean;
        s_inv  = rsqrtf(var + 1e-5f);
    }
    __syncthreads();
    const float mean = s_mean, inv = s_inv;

    const size_t bin  = ((size_t)n * Cin_tot  + (size_t)g * cpg) * PN;
    const size_t bout = ((size_t)n * Cout_tot + cbase_out + (size_t)g * cpg) * PN;
    const float4* in4 = (const float4*)(in + bin);
    float4*      out4 = (float4*)(out + bout);

    const int i0 = spl * len, i1 = i0 + len;
    for (int i = i0 + threadIdx.x; i < i1; i += 256) {
        int ch = g * cpg + (i >> 12);          // 4096 float4 per channel
        float sc = gamma[ch] * inv;
        float sh = beta[ch] - mean * sc;
        float4 v = in4[i];
        v.x = fmaxf(fmaf(v.x, sc, sh), 0.f);
        v.y = fmaxf(fmaf(v.y, sc, sh), 0.f);
        v.z = fmaxf(fmaf(v.z, sc, sh), 0.f);
        v.w = fmaxf(fmaf(v.w, sc, sh), 0.f);
        out4[i] = v;
    }
}

// ---------------------------------------------------------------------------
// Dynamic-filter branch v2: 128 threads, 32x32 px tile, 8 px/thread (1 col x
// 8 rows -> conflict-free tap LDS, weight LDS amortized to FMA balance).
// cp.async(zfill) double-buffered channel pipeline, one barrier per channel.
// grid.z = n*4 + zb, dilation order (12,8,4,1) for wave balance.
// ---------------------------------------------------------------------------
#define CPA4(dst_u32, src_ptr, sz) \
    asm volatile("cp.async.ca.shared.global [%0], [%1], 4, %2;\n" \
                 :: "r"(dst_u32), "l"(src_ptr), "r"(sz))
#define CPA_COMMIT() asm volatile("cp.async.commit_group;\n" ::: "memory")
#define CPA_WAIT0()  asm volatile("cp.async.wait_group 0;\n" ::: "memory")

__global__ void __launch_bounds__(128) branch_kernel(
    const float* __restrict__ wa, const float* __restrict__ wb,
    const float* __restrict__ wc, const float* __restrict__ wd)
{
    __shared__ float tile[2][3200];   // max 56 rows * 57 stride = 3192
    __shared__ float wsh[2][81];

    const int t  = threadIdx.x;
    const int zb = blockIdx.z & 3;
    const int n  = blockIdx.z >> 2;
    const int d  = c_rdils[zb];                 // 12,8,4,1
    const int slot = 4 - zb;                    // cat channel slot (1..4)
    const float* wcat = (zb == 0) ? wd : (zb == 1) ? wc : (zb == 2) ? wb : wa;

    const int px0 = blockIdx.x * 32;
    const int py0 = blockIdx.y * 32;
    const int WT  = 32 + 2 * d;
    const int WTp = WT | 1;

    const int tx = t & 31;          // pixel column within tile
    const int by = (t >> 5) * 8;    // base pixel row (8 rows per thread)
    const int lx = t & 31;          // loader column lane
    const int ly = t >> 5;          // loader row lane (0..3)

    const float* xd = g_cat + (size_t)n * 640 * PN;     // channels [0,128)
    const uint32_t tile_base = (uint32_t)__cvta_generic_to_shared(&tile[0][0]);
    const uint32_t wsh_base  = (uint32_t)__cvta_generic_to_shared(&wsh[0][0]);

    // stage channel c into buffer bufi (tile + optional weights), async
    auto stage = [&](int bufi, int c, bool withW) {
        const float* src = xd + (size_t)c * PN;
        for (int y = ly; y < WT; y += 4) {
            const int gy = py0 - d + y;
            const bool yok = (gy >= 0) & (gy < 128);
            const int gyc = min(max(gy, 0), 127);
            for (int x = lx; x < WT; x += 32) {
                const int gx = px0 - d + x;
                const bool ok = yok & (gx >= 0) & (gx < 128);
                const int gxc = min(max(gx, 0), 127);
                uint32_t dst = tile_base + (uint32_t)(bufi * 3200 + y * WTp + x) * 4u;
                CPA4(dst, src + gy * 0 + gyc * 128 + gxc, ok ? 4 : 0);
            }
        }
        if (withW && t < 81) {
            uint32_t dst = wsh_base + (uint32_t)(bufi * 81 + t) * 4u;
            CPA4(dst, wcat + ((size_t)(t / 9) * 128 + c) * 9 + (t % 9), 4);
        }
    };

    // ---------------- pass 1: conv logits over 128 channels ----------------
    float logit[8][9];
#pragma unroll
    for (int r = 0; r < 8; r++)
#pragma unroll
        for (int o = 0; o < 9; o++) logit[r][o] = 0.f;

    stage(0, 0, true);
    CPA_COMMIT();
    CPA_WAIT0();
    __syncthreads();

    for (int c = 0; c < 128; c++) {
        const int cur = c & 1;
        if (c < 127) { stage(cur ^ 1, c + 1, true); CPA_COMMIT(); }

        const float* tl = &tile[0][cur * 3200];
        const float* ws = &wsh[0][cur * 81];
#pragma unroll
        for (int i = 0; i < 3; i++)
#pragma unroll
            for (int j = 0; j < 3; j++) {
                const int k = i * 3 + j;
                float tap[8];
#pragma unroll
                for (int r = 0; r < 8; r++)
                    tap[r] = tl[(by + r + i * d) * WTp + tx + j * d];
#pragma unroll
                for (int o = 0; o < 9; o++) {
                    const float w = ws[o * 9 + k];
#pragma unroll
                    for (int r = 0; r < 8; r++)
                        logit[r][o] = fmaf(w, tap[r], logit[r][o]);
                }
            }

        if (c < 127) CPA_WAIT0();
        __syncthreads();
    }

    // ---------------- softmax over 9 taps per pixel (in place) -------------
#pragma unroll
    for (int r = 0; r < 8; r++) {
        float m = logit[r][0];
#pragma unroll
        for (int o = 1; o < 9; o++) m = fmaxf(m, logit[r][o]);
        float s = 0.f;
#pragma unroll
        for (int o = 0; o < 9; o++) {
            float e = __expf(logit[r][o] - m);
            logit[r][o] = e;
            s += e;
        }
        const float rcp = 1.f / s;
#pragma unroll
        for (int o = 0; o < 9; o++) logit[r][o] *= rcp;
    }

    // ---------------- pass 2: weighted 9-tap gather per channel ------------
    float* dstb = g_cat + ((size_t)n * 640 + (size_t)slot * 128) * PN
                + (size_t)(py0 + by) * 128 + px0 + tx;

    stage(0, 0, false);
    CPA_COMMIT();
    CPA_WAIT0();
    __syncthreads();

    for (int c = 0; c < 128; c++) {
        const int cur = c & 1;
        if (c < 127) { stage(cur ^ 1, c + 1, false); CPA_COMMIT(); }

        const float* tl = &tile[0][cur * 3200];
        float o_[8];
#pragma unroll
        for (int r = 0; r < 8; r++) o_[r] = 0.f;
#pragma unroll
        for (int i = 0; i < 3; i++)
#pragma unroll
            for (int j = 0; j < 3; j++) {
                const int k = i * 3 + j;
#pragma unroll
                for (int r = 0; r < 8; r++)
                    o_[r] = fmaf(tl[(by + r + i * d) * WTp + tx + j * d],
                                 logit[r][k], o_[r]);
            }

        float* dst = dstb + (size_t)c * PN;
#pragma unroll
        for (int r = 0; r < 8; r++) dst[r * 128] = o_[r];

        if (c < 127) CPA_WAIT0();
        __syncthreads();
    }
}

// ---------------------------------------------------------------------------
extern "C" void kernel_launch(void* const* d_in, const int* in_sizes, int n_in,
                              void* d_out, int out_size)
{
    const float* x   = (const float*)d_in[0];
    const float* w1  = (const float*)d_in[1];
    const float* g1g = (const float*)d_in[2];
    const float* g1b = (const float*)d_in[3];
    const float* wca = (const float*)d_in[4];
    const float* wcb = (const float*)d_in[5];
    const float* wcc = (const float*)d_in[6];
    const float* wcd = (const float*)d_in[7];
    const float* w2  = (const float*)d_in[8];
    const float* g2g = (const float*)d_in[9];
    const float* g2b = (const float*)d_in[10];
    const float* w3  = (const float*)d_in[11];
    const float* g3g = (const float*)d_in[12];
    const float* g3b = (const float*)d_in[13];
    float* out = (float*)d_out;

    float *pre, *cat, *y2;
    cudaGetSymbolAddress((void**)&pre, g_pre);
    cudaGetSymbolAddress((void**)&cat, g_cat);
    cudaGetSymbolAddress((void**)&y2,  g_y2);

    // scale1: 1x1 conv (512->128) -> GN -> ReLU (into cat channels [0,128))
    gemm_tf32_kernel<<<dim3(128, 1, 4), 256>>>(w1, x, pre, 128, 512);
    gn_stats_kernel<<<dim3(32, 4, 8), 256>>>(pre, 128, 4);
    gn_apply_kernel<<<dim3(32, 4, 8), 256>>>(pre, cat, g1g, g1b, 128, 640, 0, 4);

    // four dilated dynamic-filter branches -> cat channels [128,640)
    branch_kernel<<<dim3(4, 4, 16), 128>>>(wca, wcb, wcc, wcd);

    // scale2: 1x1 conv (640->128) -> GN -> ReLU
    gemm_tf32_kernel<<<dim3(128, 1, 4), 256>>>(w2, cat, pre, 128, 640);
    gn_stats_kernel<<<dim3(32, 4, 8), 256>>>(pre, 128, 4);
    gn_apply_kernel<<<dim3(32, 4, 8), 256>>>(pre, y2, g2g, g2b, 128, 128, 0, 4);

    // scale3: 1x1 conv (128->512) -> GN -> ReLU -> d_out
    gemm_tf32_kernel<<<dim3(128, 4, 4), 256>>>(w3, y2, pre, 512, 128);
    gn_stats_kernel<<<dim3(32, 4, 8), 256>>>(pre, 512, 16);
    gn_apply_kernel<<<dim3(32, 4, 8), 256>>>(pre, out, g3g, g3b, 512, 512, 0, 16);
}

// round 4
// speedup vs baseline: 1.6463x; 1.6463x over previous
#include <cuda_runtime.h>
#include <cstdint>

#define PN 16384      // pixels per image (128*128)
#define NIMG 4

// ---------------- scratch (static device arrays; no allocs allowed) ----------
__device__ float g_pre[4 * 512 * 16384];   // pre-GN buffer (conv outputs)
__device__ float g_cat[4 * 640 * 16384];   // [xd | branch d1,d4,d8,d12]
__device__ float g_y2 [4 * 128 * 16384];   // GN2 output
__device__ float g_part[4 * 32 * 8 * 2];   // GN partial sums

__constant__ int c_rdils[4] = {12, 8, 4, 1};   // slowest-first schedule

// ---------------------------------------------------------------------------
// tf32 tensor-core SGEMM (unchanged): Y[n][m][p] = sum_k A[m][k]*X[n][k][p]
// ---------------------------------------------------------------------------
#define AS_STR 20
#define BS_STR 136
#define AS_SZ  (128 * AS_STR)
#define BS_SZ  (16 * BS_STR)

#define CP16(dst_u32, src_ptr) \
    asm volatile("cp.async.cg.shared.global [%0], [%1], 16;\n" :: "r"(dst_u32), "l"(src_ptr))
#define CP16Z(dst_u32, src_ptr, sz) \
    asm volatile("cp.async.cg.shared.global [%0], [%1], 16, %2;\n" \
                 :: "r"(dst_u32), "l"(src_ptr), "r"(sz))
#define CPA4(dst_u32, src_ptr) \
    asm volatile("cp.async.ca.shared.global [%0], [%1], 4;\n" :: "r"(dst_u32), "l"(src_ptr))
#define CPA_COMMIT() asm volatile("cp.async.commit_group;\n" ::: "memory")
#define CPA_WAIT0()  asm volatile("cp.async.wait_group 0;\n" ::: "memory")

#define MMA_TF32(c, a, b)                                                      \
    asm volatile(                                                              \
        "mma.sync.aligned.m16n8k8.row.col.f32.tf32.tf32.f32 "                  \
        "{%0,%1,%2,%3}, {%4,%5,%6,%7}, {%8,%9}, {%0,%1,%2,%3};"                \
        : "+f"((c)[0]), "+f"((c)[1]), "+f"((c)[2]), "+f"((c)[3])               \
        : "r"((a)[0]), "r"((a)[1]), "r"((a)[2]), "r"((a)[3]),                  \
          "r"((b)[0]), "r"((b)[1]))

__global__ void __launch_bounds__(256, 2) gemm_tf32_kernel(
    const float* __restrict__ A, const float* __restrict__ X,
    float* __restrict__ Y, int M, int K)
{
    __shared__ float As[2][AS_SZ];
    __shared__ float Bs[2][BS_SZ];

    const int t  = threadIdx.x;
    const int n  = blockIdx.z;
    const int p0 = blockIdx.x * 128;
    const int m0 = blockIdx.y * 128;

    const float* Xn = X + (size_t)n * K * PN;
    float*       Yn = Y + (size_t)n * M * PN;

    const int warp = t >> 5, lane = t & 31;
    const int wm = warp & 1, wn = warp >> 1;
    const int g  = lane >> 2, tg = lane & 3;

    const uint32_t as_base = (uint32_t)__cvta_generic_to_shared(&As[0][0]);
    const uint32_t bs_base = (uint32_t)__cvta_generic_to_shared(&Bs[0][0]);

    float acc[4][4][4];
#pragma unroll
    for (int i = 0; i < 4; i++)
#pragma unroll
        for (int j = 0; j < 4; j++)
#pragma unroll
            for (int r = 0; r < 4; r++) acc[i][j][r] = 0.f;

    const int nk = K >> 4;

    auto issue_stage = [&](int bufi, int k0) {
#pragma unroll
        for (int i = 0; i < 2; i++) {
            int c   = t + i * 256;
            int row = c >> 2;
            int kc  = (c & 3) * 4;
            uint32_t dst = as_base + (uint32_t)(bufi * AS_SZ + row * AS_STR + kc) * 4u;
            CP16(dst, A + (size_t)(m0 + row) * K + k0 + kc);
        }
#pragma unroll
        for (int i = 0; i < 2; i++) {
            int c   = t + i * 256;
            int row = c >> 5;
            int pc  = (c & 31) * 4;
            uint32_t dst = bs_base + (uint32_t)(bufi * BS_SZ + row * BS_STR + pc) * 4u;
            CP16(dst, Xn + (size_t)(k0 + row) * PN + p0 + pc);
        }
    };

    issue_stage(0, 0);
    CPA_COMMIT();

    int buf = 0;
    for (int kt = 0; kt < nk; kt++) {
        if (kt + 1 < nk) {
            issue_stage(buf ^ 1, (kt + 1) * 16);
            CPA_COMMIT();
            asm volatile("cp.async.wait_group 1;\n" ::: "memory");
        } else {
            CPA_WAIT0();
        }
        __syncthreads();

        const float* as = &As[buf][0];
        const float* bs = &Bs[buf][0];
#pragma unroll
        for (int ks = 0; ks < 16; ks += 8) {
            uint32_t af[4][4], bf[4][2];
#pragma unroll
            for (int i = 0; i < 4; i++) {
                int mb = wm * 64 + i * 16;
                af[i][0] = __float_as_uint(as[(mb + g)     * AS_STR + ks + tg]);
                af[i][1] = __float_as_uint(as[(mb + g + 8) * AS_STR + ks + tg]);
                af[i][2] = __float_as_uint(as[(mb + g)     * AS_STR + ks + tg + 4]);
                af[i][3] = __float_as_uint(as[(mb + g + 8) * AS_STR + ks + tg + 4]);
            }
#pragma unroll
            for (int j = 0; j < 4; j++) {
                int nb = wn * 32 + j * 8;
                bf[j][0] = __float_as_uint(bs[(ks + tg)     * BS_STR + nb + g]);
                bf[j][1] = __float_as_uint(bs[(ks + tg + 4) * BS_STR + nb + g]);
            }
#pragma unroll
            for (int i = 0; i < 4; i++)
#pragma unroll
                for (int j = 0; j < 4; j++)
                    MMA_TF32(acc[i][j], af[i], bf[j]);
        }
        __syncthreads();
        buf ^= 1;
    }

#pragma unroll
    for (int i = 0; i < 4; i++) {
        int mrow = m0 + wm * 64 + i * 16 + g;
#pragma unroll
        for (int j = 0; j < 4; j++) {
            int col = p0 + wn * 32 + j * 8 + 2 * tg;
            *(float2*)(Yn + (size_t)mrow * PN + col)       = make_float2(acc[i][j][0], acc[i][j][1]);
            *(float2*)(Yn + (size_t)(mrow + 8) * PN + col) = make_float2(acc[i][j][2], acc[i][j][3]);
        }
    }
}

// ---------------------------------------------------------------------------
// GroupNorm split (unchanged): stats + apply.
// ---------------------------------------------------------------------------
__global__ void __launch_bounds__(256) gn_stats_kernel(
    const float* __restrict__ in, int Cin_tot, int cpg)
{
    const int g = blockIdx.x, n = blockIdx.y, spl = blockIdx.z;
    const int len = cpg * PN / 4 / 8;
    const float4* in4 = (const float4*)(in + ((size_t)n * Cin_tot + (size_t)g * cpg) * PN)
                        + (size_t)spl * len;
    float s = 0.f, q = 0.f;
    for (int i = threadIdx.x; i < len; i += 256) {
        float4 v = in4[i];
        s += v.x + v.y + v.z + v.w;
        q += v.x * v.x + v.y * v.y + v.z * v.z + v.w * v.w;
    }
    __shared__ float rs[256], rq[256];
    rs[threadIdx.x] = s; rq[threadIdx.x] = q;
    __syncthreads();
    for (int off = 128; off > 0; off >>= 1) {
        if (threadIdx.x < off) {
            rs[threadIdx.x] += rs[threadIdx.x + off];
            rq[threadIdx.x] += rq[threadIdx.x + off];
        }
        __syncthreads();
    }
    if (threadIdx.x == 0) {
        int idx = ((n * 32 + g) * 8 + spl) * 2;
        g_part[idx] = rs[0];
        g_part[idx + 1] = rq[0];
    }
}

__global__ void __launch_bounds__(256) gn_apply_kernel(
    const float* __restrict__ in, float* __restrict__ out,
    const float* __restrict__ gamma, const float* __restrict__ beta,
    int Cin_tot, int Cout_tot, int cbase_out, int cpg)
{
    const int g = blockIdx.x, n = blockIdx.y, spl = blockIdx.z;
    const int len = cpg * PN / 4 / 8;

    __shared__ float s_mean, s_inv;
    if (threadIdx.x == 0) {
        float s = 0.f, q = 0.f;
        int base = (n * 32 + g) * 8;
#pragma unroll
        for (int i = 0; i < 8; i++) {
            s += g_part[(base + i) * 2];
            q += g_part[(base + i) * 2 + 1];
        }
        float cnt = (float)(cpg * PN);
        float mean = s / cnt;
        float var  = q / cnt - mean * mean;
        s_mean = mean;
        s_inv  = rsqrtf(var + 1e-5f);
    }
    __syncthreads();
    const float mean = s_mean, inv = s_inv;

    const size_t bin  = ((size_t)n * Cin_tot  + (size_t)g * cpg) * PN;
    const size_t bout = ((size_t)n * Cout_tot + cbase_out + (size_t)g * cpg) * PN;
    const float4* in4 = (const float4*)(in + bin);
    float4*      out4 = (float4*)(out + bout);

    const int i0 = spl * len, i1 = i0 + len;
    for (int i = i0 + threadIdx.x; i < i1; i += 256) {
        int ch = g * cpg + (i >> 12);
        float sc = gamma[ch] * inv;
        float sh = beta[ch] - mean * sc;
        float4 v = in4[i];
        v.x = fmaxf(fmaf(v.x, sc, sh), 0.f);
        v.y = fmaxf(fmaf(v.y, sc, sh), 0.f);
        v.z = fmaxf(fmaf(v.z, sc, sh), 0.f);
        v.w = fmaxf(fmaf(v.w, sc, sh), 0.f);
        out4[i] = v;
    }
}

// ---------------------------------------------------------------------------
// Dynamic-filter branch v3.
// 256 threads, 32(w) x 64(h) px tile, 8 px/thread (1 col x 8 rows).
// Tile columns are the fixed aligned window [px0-16, px0+48) -> 16 float4
// chunks per row, staged with 16B cp.async zfill (never partially OOB in x).
// Double-buffered channel pipeline, one barrier per channel.
// grid = (4, 2, 16): x tiles, y tiles, n*4+zb with dilation order (12,8,4,1).
// ---------------------------------------------------------------------------
#define T_STR 68           // tile row stride (floats), 16B-aligned, 88 rows max
#define T_SZ  (88 * T_STR)

__global__ void __launch_bounds__(256) branch_kernel(
    const float* __restrict__ wa, const float* __restrict__ wb,
    const float* __restrict__ wc, const float* __restrict__ wd)
{
    __shared__ float tile[2][T_SZ];   // 47872 B
    __shared__ float wsh[2][81];      //   648 B

    const int t  = threadIdx.x;
    const int zb = blockIdx.z & 3;
    const int n  = blockIdx.z >> 2;
    const int d  = c_rdils[zb];                 // 12,8,4,1
    const int slot = 4 - zb;                    // cat channel slot (1..4)
    const float* wcat = (zb == 0) ? wd : (zb == 1) ? wc : (zb == 2) ? wb : wa;

    const int px0 = blockIdx.x * 32;
    const int py0 = blockIdx.y * 64;
    const int WT  = 64 + 2 * d;                 // halo rows (<= 88)
    const int nchunk = WT * 16;                 // float4 chunks per stage

    const int tx = t & 31;                      // pixel column (0..31)
    const int by = (t >> 5) * 8;                // base pixel row (8 rows/thread)

    const float* xd = g_cat + (size_t)n * 640 * PN;   // channels [0,128)
    const uint32_t tile_base = (uint32_t)__cvta_generic_to_shared(&tile[0][0]);
    const uint32_t wsh_base  = (uint32_t)__cvta_generic_to_shared(&wsh[0][0]);

    // per-thread weight source (only threads < 81 use it)
    const float* wptr = wcat + (size_t)(t / 9) * 128 * 9 + (t % 9);

    auto stage = [&](int bufi, int c, bool withW) {
        const float* src = xd + (size_t)c * PN;
        for (int id = t; id < nchunk; id += 256) {
            const int r  = id >> 4;
            const int gy = py0 - d + r;
            const int gx = px0 - 16 + (id & 15) * 4;
            const bool ok = ((unsigned)gy < 128u) & ((unsigned)gx < 128u);
            const int gyc = ok ? gy : 0;        // keep address in-bounds
            const int gxc = ok ? gx : 0;
            uint32_t dst = tile_base
                + (uint32_t)(bufi * T_SZ + r * T_STR + (id & 15) * 4) * 4u;
            CP16Z(dst, src + (size_t)gyc * 128 + gxc, ok ? 16 : 0);
        }
        if (withW && t < 81) {
            uint32_t dst = wsh_base + (uint32_t)(bufi * 81 + t) * 4u;
            CPA4(dst, wptr + c * 9);
        }
    };

    // ---------------- pass 1: conv logits over 128 channels ----------------
    float logit[8][9];
#pragma unroll
    for (int r = 0; r < 8; r++)
#pragma unroll
        for (int o = 0; o < 9; o++) logit[r][o] = 0.f;

    stage(0, 0, true);
    CPA_COMMIT();
    CPA_WAIT0();
    __syncthreads();

    for (int c = 0; c < 128; c++) {
        const int cur = c & 1;
        if (c < 127) { stage(cur ^ 1, c + 1, true); CPA_COMMIT(); }

        const float* tl = &tile[cur][0];
        const float* ws = &wsh[cur][0];
#pragma unroll
        for (int i = 0; i < 3; i++)
#pragma unroll
            for (int j = 0; j < 3; j++) {
                const int k = i * 3 + j;
                const int col = tx + 16 + (j - 1) * d;
                float tap[8];
#pragma unroll
                for (int r = 0; r < 8; r++)
                    tap[r] = tl[(by + r + i * d) * T_STR + col];
#pragma unroll
                for (int o = 0; o < 9; o++) {
                    const float w = ws[o * 9 + k];
#pragma unroll
                    for (int r = 0; r < 8; r++)
                        logit[r][o] = fmaf(w, tap[r], logit[r][o]);
                }
            }

        if (c < 127) CPA_WAIT0();
        __syncthreads();
    }

    // ---------------- softmax over 9 taps per pixel (in place) -------------
#pragma unroll
    for (int r = 0; r < 8; r++) {
        float m = logit[r][0];
#pragma unroll
        for (int o = 1; o < 9; o++) m = fmaxf(m, logit[r][o]);
        float s = 0.f;
#pragma unroll
        for (int o = 0; o < 9; o++) {
            float e = __expf(logit[r][o] - m);
            logit[r][o] = e;
            s += e;
        }
        const float rcp = 1.f / s;
#pragma unroll
        for (int o = 0; o < 9; o++) logit[r][o] *= rcp;
    }

    // ---------------- pass 2: weighted 9-tap gather per channel ------------
    float* dstb = g_cat + ((size_t)n * 640 + (size_t)slot * 128) * PN
                + (size_t)(py0 + by) * 128 + px0 + tx;

    stage(0, 0, false);
    CPA_COMMIT();
    CPA_WAIT0();
    __syncthreads();

    for (int c = 0; c < 128; c++) {
        const int cur = c & 1;
        if (c < 127) { stage(cur ^ 1, c + 1, false); CPA_COMMIT(); }

        const float* tl = &tile[cur][0];
        float o_[8];
#pragma unroll
        for (int r = 0; r < 8; r++) o_[r] = 0.f;
#pragma unroll
        for (int i = 0; i < 3; i++)
#pragma unroll
            for (int j = 0; j < 3; j++) {
                const int k = i * 3 + j;
                const int col = tx + 16 + (j - 1) * d;
#pragma unroll
                for (int r = 0; r < 8; r++)
                    o_[r] = fmaf(tl[(by + r + i * d) * T_STR + col],
                                 logit[r][k], o_[r]);
            }

        float* dst = dstb + (size_t)c * PN;
#pragma unroll
        for (int r = 0; r < 8; r++) dst[r * 128] = o_[r];

        if (c < 127) CPA_WAIT0();
        __syncthreads();
    }
}

// ---------------------------------------------------------------------------
extern "C" void kernel_launch(void* const* d_in, const int* in_sizes, int n_in,
                              void* d_out, int out_size)
{
    const float* x   = (const float*)d_in[0];
    const float* w1  = (const float*)d_in[1];
    const float* g1g = (const float*)d_in[2];
    const float* g1b = (const float*)d_in[3];
    const float* wca = (const float*)d_in[4];
    const float* wcb = (const float*)d_in[5];
    const float* wcc = (const float*)d_in[6];
    const float* wcd = (const float*)d_in[7];
    const float* w2  = (const float*)d_in[8];
    const float* g2g = (const float*)d_in[9];
    const float* g2b = (const float*)d_in[10];
    const float* w3  = (const float*)d_in[11];
    const float* g3g = (const float*)d_in[12];
    const float* g3b = (const float*)d_in[13];
    float* out = (float*)d_out;

    float *pre, *cat, *y2;
    cudaGetSymbolAddress((void**)&pre, g_pre);
    cudaGetSymbolAddress((void**)&cat, g_cat);
    cudaGetSymbolAddress((void**)&y2,  g_y2);

    // scale1: 1x1 conv (512->128) -> GN -> ReLU (into cat channels [0,128))
    gemm_tf32_kernel<<<dim3(128, 1, 4), 256>>>(w1, x, pre, 128, 512);
    gn_stats_kernel<<<dim3(32, 4, 8), 256>>>(pre, 128, 4);
    gn_apply_kernel<<<dim3(32, 4, 8), 256>>>(pre, cat, g1g, g1b, 128, 640, 0, 4);

    // four dilated dynamic-filter branches -> cat channels [128,640)
    branch_kernel<<<dim3(4, 2, 16), 256>>>(wca, wcb, wcc, wcd);

    // scale2: 1x1 conv (640->128) -> GN -> ReLU
    gemm_tf32_kernel<<<dim3(128, 1, 4), 256>>>(w2, cat, pre, 128, 640);
    gn_stats_kernel<<<dim3(32, 4, 8), 256>>>(pre, 128, 4);
    gn_apply_kernel<<<dim3(32, 4, 8), 256>>>(pre, y2, g2g, g2b, 128, 128, 0, 4);

    // scale3: 1x1 conv (128->512) -> GN -> ReLU -> d_out
    gemm_tf32_kernel<<<dim3(128, 4, 4), 256>>>(w3, y2, pre, 512, 128);
    gn_stats_kernel<<<dim3(32, 4, 8), 256>>>(pre, 512, 16);
    gn_apply_kernel<<<dim3(32, 4, 8), 256>>>(pre, out, g3g, g3b, 512, 512, 0, 16);
}

// round 6
// speedup vs baseline: 1.9248x; 1.1692x over previous
#include <cuda_runtime.h>
#include <cstdint>

#define PN 16384      // pixels per image (128*128)
#define NIMG 4

// ---------------- scratch (static device arrays; no allocs allowed) ----------
__device__ float g_pre[4 * 512 * 16384];   // pre-GN buffer (conv outputs)
__device__ float g_cat[4 * 640 * 16384];   // [xd | branch d1,d4,d8,d12]
__device__ float g_y2 [4 * 128 * 16384];   // GN2 output
__device__ float g_part[4 * 32 * 8 * 2];   // GN partial sums
__device__ float g_logit[16 * 9 * PN];     // dyn-filter logits [ibr][o][y][x]

__constant__ int c_dils[4] = {1, 4, 8, 12};

#define CP16(dst_u32, src_ptr) \
    asm volatile("cp.async.cg.shared.global [%0], [%1], 16;\n" :: "r"(dst_u32), "l"(src_ptr))
#define CP16Z(dst_u32, src_ptr, sz) \
    asm volatile("cp.async.cg.shared.global [%0], [%1], 16, %2;\n" \
                 :: "r"(dst_u32), "l"(src_ptr), "r"(sz))
#define CPA_COMMIT() asm volatile("cp.async.commit_group;\n" ::: "memory")
#define CPA_WAIT0()  asm volatile("cp.async.wait_group 0;\n" ::: "memory")
#define CPA_WAIT1()  asm volatile("cp.async.wait_group 1;\n" ::: "memory")

#define MMA_TF32(c, a, b)                                                      \
    asm volatile(                                                              \
        "mma.sync.aligned.m16n8k8.row.col.f32.tf32.tf32.f32 "                  \
        "{%0,%1,%2,%3}, {%4,%5,%6,%7}, {%8,%9}, {%0,%1,%2,%3};"                \
        : "+f"((c)[0]), "+f"((c)[1]), "+f"((c)[2]), "+f"((c)[3])               \
        : "r"((a)[0]), "r"((a)[1]), "r"((a)[2]), "r"((a)[3]),                  \
          "r"((b)[0]), "r"((b)[1]))

// ---------------------------------------------------------------------------
// tf32 tensor-core SGEMM (unchanged): Y[n][m][p] = sum_k A[m][k]*X[n][k][p]
// ---------------------------------------------------------------------------
#define AS_STR 20
#define BS_STR 136
#define AS_SZ  (128 * AS_STR)
#define BS_SZ  (16 * BS_STR)

__global__ void __launch_bounds__(256, 2) gemm_tf32_kernel(
    const float* __restrict__ A, const float* __restrict__ X,
    float* __restrict__ Y, int M, int K)
{
    __shared__ float As[2][AS_SZ];
    __shared__ float Bs[2][BS_SZ];

    const int t  = threadIdx.x;
    const int n  = blockIdx.z;
    const int p0 = blockIdx.x * 128;
    const int m0 = blockIdx.y * 128;

    const float* Xn = X + (size_t)n * K * PN;
    float*       Yn = Y + (size_t)n * M * PN;

    const int warp = t >> 5, lane = t & 31;
    const int wm = warp & 1, wn = warp >> 1;
    const int g  = lane >> 2, tg = lane & 3;

    const uint32_t as_base = (uint32_t)__cvta_generic_to_shared(&As[0][0]);
    const uint32_t bs_base = (uint32_t)__cvta_generic_to_shared(&Bs[0][0]);

    float acc[4][4][4];
#pragma unroll
    for (int i = 0; i < 4; i++)
#pragma unroll
        for (int j = 0; j < 4; j++)
#pragma unroll
            for (int r = 0; r < 4; r++) acc[i][j][r] = 0.f;

    const int nk = K >> 4;

    auto issue_stage = [&](int bufi, int k0) {
#pragma unroll
        for (int i = 0; i < 2; i++) {
            int c   = t + i * 256;
            int row = c >> 2;
            int kc  = (c & 3) * 4;
            uint32_t dst = as_base + (uint32_t)(bufi * AS_SZ + row * AS_STR + kc) * 4u;
            CP16(dst, A + (size_t)(m0 + row) * K + k0 + kc);
        }
#pragma unroll
        for (int i = 0; i < 2; i++) {
            int c   = t + i * 256;
            int row = c >> 5;
            int pc  = (c & 31) * 4;
            uint32_t dst = bs_base + (uint32_t)(bufi * BS_SZ + row * BS_STR + pc) * 4u;
            CP16(dst, Xn + (size_t)(k0 + row) * PN + p0 + pc);
        }
    };

    issue_stage(0, 0);
    CPA_COMMIT();

    int buf = 0;
    for (int kt = 0; kt < nk; kt++) {
        if (kt + 1 < nk) {
            issue_stage(buf ^ 1, (kt + 1) * 16);
            CPA_COMMIT();
            CPA_WAIT1();
        } else {
            CPA_WAIT0();
        }
        __syncthreads();

        const float* as = &As[buf][0];
        const float* bs = &Bs[buf][0];
#pragma unroll
        for (int ks = 0; ks < 16; ks += 8) {
            uint32_t af[4][4], bf[4][2];
#pragma unroll
            for (int i = 0; i < 4; i++) {
                int mb = wm * 64 + i * 16;
                af[i][0] = __float_as_uint(as[(mb + g)     * AS_STR + ks + tg]);
                af[i][1] = __float_as_uint(as[(mb + g + 8) * AS_STR + ks + tg]);
                af[i][2] = __float_as_uint(as[(mb + g)     * AS_STR + ks + tg + 4]);
                af[i][3] = __float_as_uint(as[(mb + g + 8) * AS_STR + ks + tg + 4]);
            }
#pragma unroll
            for (int j = 0; j < 4; j++) {
                int nb = wn * 32 + j * 8;
                bf[j][0] = __float_as_uint(bs[(ks + tg)     * BS_STR + nb + g]);
                bf[j][1] = __float_as_uint(bs[(ks + tg + 4) * BS_STR + nb + g]);
            }
#pragma unroll
            for (int i = 0; i < 4; i++)
#pragma unroll
                for (int j = 0; j < 4; j++)
                    MMA_TF32(acc[i][j], af[i], bf[j]);
        }
        __syncthreads();
        buf ^= 1;
    }

#pragma unroll
    for (int i = 0; i < 4; i++) {
        int mrow = m0 + wm * 64 + i * 16 + g;
#pragma unroll
        for (int j = 0; j < 4; j++) {
            int col = p0 + wn * 32 + j * 8 + 2 * tg;
            *(float2*)(Yn + (size_t)mrow * PN + col)       = make_float2(acc[i][j][0], acc[i][j][1]);
            *(float2*)(Yn + (size_t)(mrow + 8) * PN + col) = make_float2(acc[i][j][2], acc[i][j][3]);
        }
    }
}

// ---------------------------------------------------------------------------
// GroupNorm split (unchanged): stats + apply.
// ---------------------------------------------------------------------------
__global__ void __launch_bounds__(256) gn_stats_kernel(
    const float* __restrict__ in, int Cin_tot, int cpg)
{
    const int g = blockIdx.x, n = blockIdx.y, spl = blockIdx.z;
    const int len = cpg * PN / 4 / 8;
    const float4* in4 = (const float4*)(in + ((size_t)n * Cin_tot + (size_t)g * cpg) * PN)
                        + (size_t)spl * len;
    float s = 0.f, q = 0.f;
    for (int i = threadIdx.x; i < len; i += 256) {
        float4 v = in4[i];
        s += v.x + v.y + v.z + v.w;
        q += v.x * v.x + v.y * v.y + v.z * v.z + v.w * v.w;
    }
    __shared__ float rs[256], rq[256];
    rs[threadIdx.x] = s; rq[threadIdx.x] = q;
    __syncthreads();
    for (int off = 128; off > 0; off >>= 1) {
        if (threadIdx.x < off) {
            rs[threadIdx.x] += rs[threadIdx.x + off];
            rq[threadIdx.x] += rq[threadIdx.x + off];
        }
        __syncthreads();
    }
    if (threadIdx.x == 0) {
        int idx = ((n * 32 + g) * 8 + spl) * 2;
        g_part[idx] = rs[0];
        g_part[idx + 1] = rq[0];
    }
}

__global__ void __launch_bounds__(256) gn_apply_kernel(
    const float* __restrict__ in, float* __restrict__ out,
    const float* __restrict__ gamma, const float* __restrict__ beta,
    int Cin_tot, int Cout_tot, int cbase_out, int cpg)
{
    const int g = blockIdx.x, n = blockIdx.y, spl = blockIdx.z;
    const int len = cpg * PN / 4 / 8;

    __shared__ float s_mean, s_inv;
    if (threadIdx.x == 0) {
        float s = 0.f, q = 0.f;
        int base = (n * 32 + g) * 8;
#pragma unroll
        for (int i = 0; i < 8; i++) {
            s += g_part[(base + i) * 2];
            q += g_part[(base + i) * 2 + 1];
        }
        float cnt = (float)(cpg * PN);
        float mean = s / cnt;
        float var  = q / cnt - mean * mean;
        s_mean = mean;
        s_inv  = rsqrtf(var + 1e-5f);
    }
    __syncthreads();
    const float mean = s_mean, inv = s_inv;

    const size_t bin  = ((size_t)n * Cin_tot  + (size_t)g * cpg) * PN;
    const size_t bout = ((size_t)n * Cout_tot + cbase_out + (size_t)g * cpg) * PN;
    const float4* in4 = (const float4*)(in + bin);
    float4*      out4 = (float4*)(out + bout);

    const int i0 = spl * len, i1 = i0 + len;
    for (int i = i0 + threadIdx.x; i < i1; i += 256) {
        int ch = g * cpg + (i >> 12);
        float sc = gamma[ch] * inv;
        float sh = beta[ch] - mean * sc;
        float4 v = in4[i];
        v.x = fmaxf(fmaf(v.x, sc, sh), 0.f);
        v.y = fmaxf(fmaf(v.y, sc, sh), 0.f);
        v.z = fmaxf(fmaf(v.z, sc, sh), 0.f);
        v.w = fmaxf(fmaf(v.w, sc, sh), 0.f);
        out4[i] = v;
    }
}

// ---------------------------------------------------------------------------
// Dyn-filter pass 1 on TENSOR CORES: logits L[o,p] = sum_k sum_c W_k[o,c]*X[c,p+shift_k]
// = 9 shifted GEMMs (M=16 pad of 9, K=128 channels in chunks of 8, N=128 px = 1 row).
// Block: 128 thr (4 warps), one image row y, one (img, branch). grid (128, 16).
// X smem: 8 ch planes x 3 rows x 152 cols (12-col zero borders, zeroed once).
// W smem: 16 x 76 (rows 9-15 garbage -> D rows 9-15 discarded; rows independent).
// ---------------------------------------------------------------------------
#define XP_ROW   152
#define XP_PLANE (3 * XP_ROW)      // 456: 8*tg + g distinct mod 32 -> conflict-free B
#define XP_SZ    (8 * XP_PLANE)    // 3648 floats
#define WS_STR   76                // 12*g + 9*tg injective mod 32 -> conflict-free A
#define WS_SZ    (16 * WS_STR)     // 1216 floats

__global__ void __launch_bounds__(128) dyn_logits_kernel(
    const float* __restrict__ wa, const float* __restrict__ wb,
    const float* __restrict__ wc, const float* __restrict__ wd)
{
    __shared__ float Xs[2][XP_SZ];
    __shared__ float Ws[2][WS_SZ];

    const int t   = threadIdx.x;
    const int y   = blockIdx.x;
    const int ibr = blockIdx.y;
    const int b   = ibr & 3;
    const int n   = ibr >> 2;
    const int d   = c_dils[b];
    const float* wcat = (b == 0) ? wa : (b == 1) ? wb : (b == 2) ? wc : wd;
    const float* xd   = g_cat + (size_t)n * 640 * PN;

    const int warp = t >> 5, lane = t & 31;
    const int g = lane >> 2, tg = lane & 3;

    const uint32_t xs_base = (uint32_t)__cvta_generic_to_shared(&Xs[0][0]);
    const uint32_t ws_base = (uint32_t)__cvta_generic_to_shared(&Ws[0][0]);

    // zero X smem once; borders [0,12) & [140,152) stay zero forever
    for (int i = t; i < 2 * XP_SZ; i += 128) (&Xs[0][0])[i] = 0.f;
    __syncthreads();

    // 8 ch * 3 rows * 32 chunks(16B) = 768 chunks per stage
    auto stageX = [&](int bufi, int chunk) {
#pragma unroll
        for (int id = t; id < 768; id += 128) {
            const int cc  = id / 96;
            const int rem = id % 96;
            const int i   = rem >> 5;          // 0..2
            const int q   = rem & 31;          // 0..31 -> cols q*4..q*4+3
            const int gy  = y + (i - 1) * d;
            const bool ok = (unsigned)gy < 128u;
            uint32_t dst = xs_base
                + (uint32_t)(bufi * XP_SZ + cc * XP_PLANE + i * XP_ROW + 12 + q * 4) * 4u;
            const float* src = xd + (size_t)(chunk * 8 + cc) * PN
                             + (size_t)(ok ? gy : 0) * 128 + q * 4;
            CP16Z(dst, src, ok ? 16 : 0);
        }
    };
    auto stageW = [&](int bufi, int chunk) {
        for (int id = t; id < 162; id += 128) {      // 9 o * 18 chunks16B (72 floats)
            const int o = id / 18;
            const int q = id % 18;
            uint32_t dst = ws_base + (uint32_t)(bufi * WS_SZ + o * WS_STR + q * 4) * 4u;
            CP16(dst, wcat + (size_t)o * 1152 + chunk * 72 + q * 4);
        }
    };

    float acc[4][4];
#pragma unroll
    for (int jt = 0; jt < 4; jt++)
#pragma unroll
        for (int r = 0; r < 4; r++) acc[jt][r] = 0.f;

    stageX(0, 0); stageW(0, 0);
    CPA_COMMIT();

    for (int ch = 0; ch < 16; ch++) {
        const int cur = ch & 1;
        if (ch < 15) {
            stageX(cur ^ 1, ch + 1); stageW(cur ^ 1, ch + 1);
            CPA_COMMIT();
            CPA_WAIT1();
        } else {
            CPA_WAIT0();
        }
        __syncthreads();

        const float* xs = &Xs[cur][0];
        const float* ws = &Ws[cur][0];
#pragma unroll
        for (int i = 0; i < 3; i++)
#pragma unroll
            for (int j = 0; j < 3; j++) {
                const int k = i * 3 + j;
                uint32_t af[4];
                af[0] = __float_as_uint(ws[(g)     * WS_STR + tg * 9 + k]);
                af[1] = __float_as_uint(ws[(g + 8) * WS_STR + tg * 9 + k]);
                af[2] = __float_as_uint(ws[(g)     * WS_STR + (tg + 4) * 9 + k]);
                af[3] = __float_as_uint(ws[(g + 8) * WS_STR + (tg + 4) * 9 + k]);
                const int srow = i * XP_ROW + 12 + (j - 1) * d + warp * 32 + g;
#pragma unroll
                for (int jt = 0; jt < 4; jt++) {
                    uint32_t bf[2];
                    bf[0] = __float_as_uint(xs[(tg)     * XP_PLANE + srow + jt * 8]);
                    bf[1] = __float_as_uint(xs[(tg + 4) * XP_PLANE + srow + jt * 8]);
                    MMA_TF32(acc[jt], af, bf);
                }
            }
        __syncthreads();
    }

    // store logits: thread holds L[o=g][x], L[o=g][x+1] (c0,c1); g==0 also row 8 (c2,c3)
    float* Lb = g_logit + (size_t)ibr * 9 * PN + (size_t)y * 128;
#pragma unroll
    for (int jt = 0; jt < 4; jt++) {
        const int x = warp * 32 + jt * 8 + 2 * tg;
        *(float2*)(Lb + (size_t)g * PN + x) = make_float2(acc[jt][0], acc[jt][1]);
        if (g == 0)
            *(float2*)(Lb + (size_t)8 * PN + x) = make_float2(acc[jt][2], acc[jt][3]);
    }
}

// ---------------------------------------------------------------------------
// Dyn-filter pass 2: read logits -> softmax -> per-channel 9-tap weighted gather.
// 256 thr, 32(w) x 64(h) px tile, 8 px/thread. Double-buffered channel pipeline.
// grid = (4, 2, 16).
// ---------------------------------------------------------------------------
#define T_STR 68
#define T_SZ  (88 * T_STR)

__global__ void __launch_bounds__(256) branch_apply_kernel()
{
    __shared__ float tile[2][T_SZ];

    const int t   = threadIdx.x;
    const int ibr = blockIdx.z;
    const int b   = ibr & 3;
    const int n   = ibr >> 2;
    const int d   = c_dils[b];
    const int slot = 1 + b;

    const int px0 = blockIdx.x * 32;
    const int py0 = blockIdx.y * 64;
    const int WT  = 64 + 2 * d;
    const int nchunk = WT * 16;

    const int tx = t & 31;
    const int by = (t >> 5) * 8;

    const float* xd = g_cat + (size_t)n * 640 * PN;
    const uint32_t tile_base = (uint32_t)__cvta_generic_to_shared(&tile[0][0]);

    auto stage = [&](int bufi, int c) {
        const float* src = xd + (size_t)c * PN;
        for (int id = t; id < nchunk; id += 256) {
            const int r  = id >> 4;
            const int gy = py0 - d + r;
            const int gx = px0 - 16 + (id & 15) * 4;
            const bool ok = ((unsigned)gy < 128u) & ((unsigned)gx < 128u);
            const int gyc = ok ? gy : 0;
            const int gxc = ok ? gx : 0;
            uint32_t dst = tile_base
                + (uint32_t)(bufi * T_SZ + r * T_STR + (id & 15) * 4) * 4u;
            CP16Z(dst, src + (size_t)gyc * 128 + gxc, ok ? 16 : 0);
        }
    };

    stage(0, 0);
    CPA_COMMIT();

    // ---- load logits + softmax -> f in registers ----
    float f[8][9];
    {
        const float* Lb = g_logit + (size_t)ibr * 9 * PN
                        + (size_t)(py0 + by) * 128 + px0 + tx;
#pragma unroll
        for (int o = 0; o < 9; o++)
#pragma unroll
            for (int r = 0; r < 8; r++)
                f[r][o] = Lb[(size_t)o * PN + r * 128];
#pragma unroll
        for (int r = 0; r < 8; r++) {
            float m = f[r][0];
#pragma unroll
            for (int o = 1; o < 9; o++) m = fmaxf(m, f[r][o]);
            float s = 0.f;
#pragma unroll
            for (int o = 0; o < 9; o++) {
                float e = __expf(f[r][o] - m);
                f[r][o] = e;
                s += e;
            }
            const float rcp = 1.f / s;
#pragma unroll
            for (int o = 0; o < 9; o++) f[r][o] *= rcp;
        }
    }

    float* dstb = g_cat + ((size_t)n * 640 + (size_t)slot * 128) * PN
                + (size_t)(py0 + by) * 128 + px0 + tx;

    CPA_WAIT0();
    __syncthreads();

    for (int c = 0; c < 128; c++) {
        const int cur = c & 1;
        if (c < 127) { stage(cur ^ 1, c + 1); CPA_COMMIT(); }

        const float* tl = &tile[cur][0];
        float o_[8];
#pragma unroll
        for (int r = 0; r < 8; r++) o_[r] = 0.f;
#pragma unroll
        for (int i = 0; i < 3; i++)
#pragma unroll
            for (int j = 0; j < 3; j++) {
                const int k = i * 3 + j;
                const int col = tx + 16 + (j - 1) * d;
#pragma unroll
                for (int r = 0; r < 8; r++)
                    o_[r] = fmaf(tl[(by + r + i * d) * T_STR + col],
                                 f[r][k], o_[r]);
            }

        float* dst = dstb + (size_t)c * PN;
#pragma unroll
        for (int r = 0; r < 8; r++) dst[r * 128] = o_[r];

        if (c < 127) CPA_WAIT0();
        __syncthreads();
    }
}

// ---------------------------------------------------------------------------
extern "C" void kernel_launch(void* const* d_in, const int* in_sizes, int n_in,
                              void* d_out, int out_size)
{
    const float* x   = (const float*)d_in[0];
    const float* w1  = (const float*)d_in[1];
    const float* g1g = (const float*)d_in[2];
    const float* g1b = (const float*)d_in[3];
    const float* wca = (const float*)d_in[4];
    const float* wcb = (const float*)d_in[5];
    const float* wcc = (const float*)d_in[6];
    const float* wcd = (const float*)d_in[7];
    const float* w2  = (const float*)d_in[8];
    const float* g2g = (const float*)d_in[9];
    const float* g2b = (const float*)d_in[10];
    const float* w3  = (const float*)d_in[11];
    const float* g3g = (const float*)d_in[12];
    const float* g3b = (const float*)d_in[13];
    float* out = (float*)d_out;

    float *pre, *cat, *y2;
    cudaGetSymbolAddress((void**)&pre, g_pre);
    cudaGetSymbolAddress((void**)&cat, g_cat);
    cudaGetSymbolAddress((void**)&y2,  g_y2);

    // scale1: 1x1 conv (512->128) -> GN -> ReLU (into cat channels [0,128))
    gemm_tf32_kernel<<<dim3(128, 1, 4), 256>>>(w1, x, pre, 128, 512);
    gn_stats_kernel<<<dim3(32, 4, 8), 256>>>(pre, 128, 4);
    gn_apply_kernel<<<dim3(32, 4, 8), 256>>>(pre, cat, g1g, g1b, 128, 640, 0, 4);

    // dyn-filter branches: tensor-core logits, then softmax+gather
    dyn_logits_kernel<<<dim3(128, 16), 128>>>(wca, wcb, wcc, wcd);
    branch_apply_kernel<<<dim3(4, 2, 16), 256>>>();

    // scale2: 1x1 conv (640->128) -> GN -> ReLU
    gemm_tf32_kernel<<<dim3(128, 1, 4), 256>>>(w2, cat, pre, 128, 640);
    gn_stats_kernel<<<dim3(32, 4, 8), 256>>>(pre, 128, 4);
    gn_apply_kernel<<<dim3(32, 4, 8), 256>>>(pre, y2, g2g, g2b, 128, 128, 0, 4);

    // scale3: 1x1 conv (128->512) -> GN -> ReLU -> d_out
    gemm_tf32_kernel<<<dim3(128, 4, 4), 256>>>(w3, y2, pre, 512, 128);
    gn_stats_kernel<<<dim3(32, 4, 8), 256>>>(pre, 512, 16);
    gn_apply_kernel<<<dim3(32, 4, 8), 256>>>(pre, out, g3g, g3b, 512, 512, 0, 16);
}

// round 7
// speedup vs baseline: 1.9807x; 1.0290x over previous
#include <cuda_runtime.h>
#include <cstdint>

#define PN 16384      // pixels per image (128*128)
#define NIMG 4

// ---------------- scratch (static device arrays; no allocs allowed) ----------
__device__ float g_pre[4 * 512 * 16384];   // pre-GN buffer (conv outputs)
__device__ float g_cat[4 * 640 * 16384];   // [xd | branch d1,d4,d8,d12]
__device__ float g_y2 [4 * 128 * 16384];   // GN2 output
__device__ float g_part[4 * 32 * 8 * 2];   // GN partial sums
__device__ float g_logit[16 * 9 * PN];     // dyn-filter logits [ibr][o][y][x]

__constant__ int c_dils[4] = {1, 4, 8, 12};

#define CP16(dst_u32, src_ptr) \
    asm volatile("cp.async.cg.shared.global [%0], [%1], 16;\n" :: "r"(dst_u32), "l"(src_ptr))
#define CP16Z(dst_u32, src_ptr, sz) \
    asm volatile("cp.async.cg.shared.global [%0], [%1], 16, %2;\n" \
                 :: "r"(dst_u32), "l"(src_ptr), "r"(sz))
#define CPA_COMMIT() asm volatile("cp.async.commit_group;\n" ::: "memory")
#define CPA_WAIT0()  asm volatile("cp.async.wait_group 0;\n" ::: "memory")
#define CPA_WAIT1()  asm volatile("cp.async.wait_group 1;\n" ::: "memory")
#define CPA_WAIT2()  asm volatile("cp.async.wait_group 2;\n" ::: "memory")

#define MMA_TF32(c, a, b)                                                      \
    asm volatile(                                                              \
        "mma.sync.aligned.m16n8k8.row.col.f32.tf32.tf32.f32 "                  \
        "{%0,%1,%2,%3}, {%4,%5,%6,%7}, {%8,%9}, {%0,%1,%2,%3};"                \
        : "+f"((c)[0]), "+f"((c)[1]), "+f"((c)[2]), "+f"((c)[3])               \
        : "r"((a)[0]), "r"((a)[1]), "r"((a)[2]), "r"((a)[3]),                  \
          "r"((b)[0]), "r"((b)[1]))

// ---------------------------------------------------------------------------
// tf32 tensor-core SGEMM, 3-stage cp.async pipeline (dynamic smem).
// Y[n][m][p] = sum_k A[m][k]*X[n][k][p]. Block tile 128x128x16, 256 thr.
// ---------------------------------------------------------------------------
#define AS_STR 20
#define BS_STR 136
#define AS_SZ  (128 * AS_STR)
#define BS_SZ  (16 * BS_STR)
#define GEMM_SMEM ((3 * (AS_SZ + BS_SZ)) * 4)   // 56832 B

__global__ void __launch_bounds__(256, 2) gemm_tf32_kernel(
    const float* __restrict__ A, const float* __restrict__ X,
    float* __restrict__ Y, int M, int K)
{
    extern __shared__ float smem_dyn[];
    float* As = smem_dyn;                 // 3 stages of AS_SZ
    float* Bs = smem_dyn + 3 * AS_SZ;     // 3 stages of BS_SZ

    const int t  = threadIdx.x;
    const int n  = blockIdx.z;
    const int p0 = blockIdx.x * 128;
    const int m0 = blockIdx.y * 128;

    const float* Xn = X + (size_t)n * K * PN;
    float*       Yn = Y + (size_t)n * M * PN;

    const int warp = t >> 5, lane = t & 31;
    const int wm = warp & 1, wn = warp >> 1;
    const int g  = lane >> 2, tg = lane & 3;

    const uint32_t as_base = (uint32_t)__cvta_generic_to_shared(As);
    const uint32_t bs_base = (uint32_t)__cvta_generic_to_shared(Bs);

    float acc[4][4][4];
#pragma unroll
    for (int i = 0; i < 4; i++)
#pragma unroll
        for (int j = 0; j < 4; j++)
#pragma unroll
            for (int r = 0; r < 4; r++) acc[i][j][r] = 0.f;

    const int nk = K >> 4;

    auto issue_stage = [&](int bufi, int k0) {
#pragma unroll
        for (int i = 0; i < 2; i++) {
            int c   = t + i * 256;
            int row = c >> 2;
            int kc  = (c & 3) * 4;
            uint32_t dst = as_base + (uint32_t)(bufi * AS_SZ + row * AS_STR + kc) * 4u;
            CP16(dst, A + (size_t)(m0 + row) * K + k0 + kc);
        }
#pragma unroll
        for (int i = 0; i < 2; i++) {
            int c   = t + i * 256;
            int row = c >> 5;
            int pc  = (c & 31) * 4;
            uint32_t dst = bs_base + (uint32_t)(bufi * BS_SZ + row * BS_STR + pc) * 4u;
            CP16(dst, Xn + (size_t)(k0 + row) * PN + p0 + pc);
        }
    };

    // prologue: 2 stages in flight
    issue_stage(0, 0);
    CPA_COMMIT();
    if (nk > 1) { issue_stage(1, 16); CPA_COMMIT(); }

    for (int kt = 0; kt < nk; kt++) {
        if (kt + 2 < nk) {
            issue_stage((kt + 2) % 3, (kt + 2) * 16);
            CPA_COMMIT();
            CPA_WAIT2();
        } else if (kt + 1 < nk) {
            CPA_WAIT1();
        } else {
            CPA_WAIT0();
        }
        __syncthreads();

        const float* as = As + (kt % 3) * AS_SZ;
        const float* bs = Bs + (kt % 3) * BS_SZ;
#pragma unroll
        for (int ks = 0; ks < 16; ks += 8) {
            uint32_t af[4][4], bf[4][2];
#pragma unroll
            for (int i = 0; i < 4; i++) {
                int mb = wm * 64 + i * 16;
                af[i][0] = __float_as_uint(as[(mb + g)     * AS_STR + ks + tg]);
                af[i][1] = __float_as_uint(as[(mb + g + 8) * AS_STR + ks + tg]);
                af[i][2] = __float_as_uint(as[(mb + g)     * AS_STR + ks + tg + 4]);
                af[i][3] = __float_as_uint(as[(mb + g + 8) * AS_STR + ks + tg + 4]);
            }
#pragma unroll
            for (int j = 0; j < 4; j++) {
                int nb = wn * 32 + j * 8;
                bf[j][0] = __float_as_uint(bs[(ks + tg)     * BS_STR + nb + g]);
                bf[j][1] = __float_as_uint(bs[(ks + tg + 4) * BS_STR + nb + g]);
            }
#pragma unroll
            for (int i = 0; i < 4; i++)
#pragma unroll
                for (int j = 0; j < 4; j++)
                    MMA_TF32(acc[i][j], af[i], bf[j]);
        }
        __syncthreads();
    }

#pragma unroll
    for (int i = 0; i < 4; i++) {
        int mrow = m0 + wm * 64 + i * 16 + g;
#pragma unroll
        for (int j = 0; j < 4; j++) {
            int col = p0 + wn * 32 + j * 8 + 2 * tg;
            *(float2*)(Yn + (size_t)mrow * PN + col)       = make_float2(acc[i][j][0], acc[i][j][1]);
            *(float2*)(Yn + (size_t)(mrow + 8) * PN + col) = make_float2(acc[i][j][2], acc[i][j][3]);
        }
    }
}

// ---------------------------------------------------------------------------
// GroupNorm split (unchanged): stats + apply.
// ---------------------------------------------------------------------------
__global__ void __launch_bounds__(256) gn_stats_kernel(
    const float* __restrict__ in, int Cin_tot, int cpg)
{
    const int g = blockIdx.x, n = blockIdx.y, spl = blockIdx.z;
    const int len = cpg * PN / 4 / 8;
    const float4* in4 = (const float4*)(in + ((size_t)n * Cin_tot + (size_t)g * cpg) * PN)
                        + (size_t)spl * len;
    float s = 0.f, q = 0.f;
    for (int i = threadIdx.x; i < len; i += 256) {
        float4 v = in4[i];
        s += v.x + v.y + v.z + v.w;
        q += v.x * v.x + v.y * v.y + v.z * v.z + v.w * v.w;
    }
    __shared__ float rs[256], rq[256];
    rs[threadIdx.x] = s; rq[threadIdx.x] = q;
    __syncthreads();
    for (int off = 128; off > 0; off >>= 1) {
        if (threadIdx.x < off) {
            rs[threadIdx.x] += rs[threadIdx.x + off];
            rq[threadIdx.x] += rq[threadIdx.x + off];
        }
        __syncthreads();
    }
    if (threadIdx.x == 0) {
        int idx = ((n * 32 + g) * 8 + spl) * 2;
        g_part[idx] = rs[0];
        g_part[idx + 1] = rq[0];
    }
}

__global__ void __launch_bounds__(256) gn_apply_kernel(
    const float* __restrict__ in, float* __restrict__ out,
    const float* __restrict__ gamma, const float* __restrict__ beta,
    int Cin_tot, int Cout_tot, int cbase_out, int cpg)
{
    const int g = blockIdx.x, n = blockIdx.y, spl = blockIdx.z;
    const int len = cpg * PN / 4 / 8;

    __shared__ float s_mean, s_inv;
    if (threadIdx.x == 0) {
        float s = 0.f, q = 0.f;
        int base = (n * 32 + g) * 8;
#pragma unroll
        for (int i = 0; i < 8; i++) {
            s += g_part[(base + i) * 2];
            q += g_part[(base + i) * 2 + 1];
        }
        float cnt = (float)(cpg * PN);
        float mean = s / cnt;
        float var  = q / cnt - mean * mean;
        s_mean = mean;
        s_inv  = rsqrtf(var + 1e-5f);
    }
    __syncthreads();
    const float mean = s_mean, inv = s_inv;

    const size_t bin  = ((size_t)n * Cin_tot  + (size_t)g * cpg) * PN;
    const size_t bout = ((size_t)n * Cout_tot + cbase_out + (size_t)g * cpg) * PN;
    const float4* in4 = (const float4*)(in + bin);
    float4*      out4 = (float4*)(out + bout);

    const int i0 = spl * len, i1 = i0 + len;
    for (int i = i0 + threadIdx.x; i < i1; i += 256) {
        int ch = g * cpg + (i >> 12);
        float sc = gamma[ch] * inv;
        float sh = beta[ch] - mean * sc;
        float4 v = in4[i];
        v.x = fmaxf(fmaf(v.x, sc, sh), 0.f);
        v.y = fmaxf(fmaf(v.y, sc, sh), 0.f);
        v.z = fmaxf(fmaf(v.z, sc, sh), 0.f);
        v.w = fmaxf(fmaf(v.w, sc, sh), 0.f);
        out4[i] = v;
    }
}

// ---------------------------------------------------------------------------
// Dyn-filter pass 1 on tensor cores (unchanged from R6).
// ---------------------------------------------------------------------------
#define XP_ROW   152
#define XP_PLANE (3 * XP_ROW)
#define XP_SZ    (8 * XP_PLANE)
#define WS_STR   76
#define WS_SZ    (16 * WS_STR)

__global__ void __launch_bounds__(128) dyn_logits_kernel(
    const float* __restrict__ wa, const float* __restrict__ wb,
    const float* __restrict__ wc, const float* __restrict__ wd)
{
    __shared__ float Xs[2][XP_SZ];
    __shared__ float Ws[2][WS_SZ];

    const int t   = threadIdx.x;
    const int y   = blockIdx.x;
    const int ibr = blockIdx.y;
    const int b   = ibr & 3;
    const int n   = ibr >> 2;
    const int d   = c_dils[b];
    const float* wcat = (b == 0) ? wa : (b == 1) ? wb : (b == 2) ? wc : wd;
    const float* xd   = g_cat + (size_t)n * 640 * PN;

    const int warp = t >> 5, lane = t & 31;
    const int g = lane >> 2, tg = lane & 3;

    const uint32_t xs_base = (uint32_t)__cvta_generic_to_shared(&Xs[0][0]);
    const uint32_t ws_base = (uint32_t)__cvta_generic_to_shared(&Ws[0][0]);

    for (int i = t; i < 2 * XP_SZ; i += 128) (&Xs[0][0])[i] = 0.f;
    __syncthreads();

    auto stageX = [&](int bufi, int chunk) {
#pragma unroll
        for (int id = t; id < 768; id += 128) {
            const int cc  = id / 96;
            const int rem = id % 96;
            const int i   = rem >> 5;
            const int q   = rem & 31;
            const int gy  = y + (i - 1) * d;
            const bool ok = (unsigned)gy < 128u;
            uint32_t dst = xs_base
                + (uint32_t)(bufi * XP_SZ + cc * XP_PLANE + i * XP_ROW + 12 + q * 4) * 4u;
            const float* src = xd + (size_t)(chunk * 8 + cc) * PN
                             + (size_t)(ok ? gy : 0) * 128 + q * 4;
            CP16Z(dst, src, ok ? 16 : 0);
        }
    };
    auto stageW = [&](int bufi, int chunk) {
        for (int id = t; id < 162; id += 128) {
            const int o = id / 18;
            const int q = id % 18;
            uint32_t dst = ws_base + (uint32_t)(bufi * WS_SZ + o * WS_STR + q * 4) * 4u;
            CP16(dst, wcat + (size_t)o * 1152 + chunk * 72 + q * 4);
        }
    };

    float acc[4][4];
#pragma unroll
    for (int jt = 0; jt < 4; jt++)
#pragma unroll
        for (int r = 0; r < 4; r++) acc[jt][r] = 0.f;

    stageX(0, 0); stageW(0, 0);
    CPA_COMMIT();

    for (int ch = 0; ch < 16; ch++) {
        const int cur = ch & 1;
        if (ch < 15) {
            stageX(cur ^ 1, ch + 1); stageW(cur ^ 1, ch + 1);
            CPA_COMMIT();
            CPA_WAIT1();
        } else {
            CPA_WAIT0();
        }
        __syncthreads();

        const float* xs = &Xs[cur][0];
        const float* ws = &Ws[cur][0];
#pragma unroll
        for (int i = 0; i < 3; i++)
#pragma unroll
            for (int j = 0; j < 3; j++) {
                const int k = i * 3 + j;
                uint32_t af[4];
                af[0] = __float_as_uint(ws[(g)     * WS_STR + tg * 9 + k]);
                af[1] = __float_as_uint(ws[(g + 8) * WS_STR + tg * 9 + k]);
                af[2] = __float_as_uint(ws[(g)     * WS_STR + (tg + 4) * 9 + k]);
                af[3] = __float_as_uint(ws[(g + 8) * WS_STR + (tg + 4) * 9 + k]);
                const int srow = i * XP_ROW + 12 + (j - 1) * d + warp * 32 + g;
#pragma unroll
                for (int jt = 0; jt < 4; jt++) {
                    uint32_t bf[2];
                    bf[0] = __float_as_uint(xs[(tg)     * XP_PLANE + srow + jt * 8]);
                    bf[1] = __float_as_uint(xs[(tg + 4) * XP_PLANE + srow + jt * 8]);
                    MMA_TF32(acc[jt], af, bf);
                }
            }
        __syncthreads();
    }

    float* Lb = g_logit + (size_t)ibr * 9 * PN + (size_t)y * 128;
#pragma unroll
    for (int jt = 0; jt < 4; jt++) {
        const int x = warp * 32 + jt * 8 + 2 * tg;
        *(float2*)(Lb + (size_t)g * PN + x) = make_float2(acc[jt][0], acc[jt][1]);
        if (g == 0)
            *(float2*)(Lb + (size_t)8 * PN + x) = make_float2(acc[jt][2], acc[jt][3]);
    }
}

// ---------------------------------------------------------------------------
// Dyn-filter pass 2: 32x32 tile, 256 thr, 4 px/thread, grid (4,4,16).
// ---------------------------------------------------------------------------
#define T_STR 68
#define T_SZ  (56 * T_STR)          // 56 rows max (32 + 2*12)

__global__ void __launch_bounds__(256) branch_apply_kernel()
{
    __shared__ float tile[2][T_SZ];  // 30.5 KB

    const int t   = threadIdx.x;
    const int ibr = blockIdx.z;
    const int b   = ibr & 3;
    const int n   = ibr >> 2;
    const int d   = c_dils[b];
    const int slot = 1 + b;

    const int px0 = blockIdx.x * 32;
    const int py0 = blockIdx.y * 32;
    const int WT  = 32 + 2 * d;
    const int nchunk = WT * 16;

    const int tx = t & 31;
    const int by = (t >> 5) * 4;     // 8 warps x 4 rows = 32 rows

    const float* xd = g_cat + (size_t)n * 640 * PN;
    const uint32_t tile_base = (uint32_t)__cvta_generic_to_shared(&tile[0][0]);

    auto stage = [&](int bufi, int c) {
        const float* src = xd + (size_t)c * PN;
        for (int id = t; id < nchunk; id += 256) {
            const int r  = id >> 4;
            const int gy = py0 - d + r;
            const int gx = px0 - 16 + (id & 15) * 4;
            const bool ok = ((unsigned)gy < 128u) & ((unsigned)gx < 128u);
            const int gyc = ok ? gy : 0;
            const int gxc = ok ? gx : 0;
            uint32_t dst = tile_base
                + (uint32_t)(bufi * T_SZ + r * T_STR + (id & 15) * 4) * 4u;
            CP16Z(dst, src + (size_t)gyc * 128 + gxc, ok ? 16 : 0);
        }
    };

    stage(0, 0);
    CPA_COMMIT();

    // ---- load logits + softmax -> f in registers ----
    float f[4][9];
    {
        const float* Lb = g_logit + (size_t)ibr * 9 * PN
                        + (size_t)(py0 + by) * 128 + px0 + tx;
#pragma unroll
        for (int o = 0; o < 9; o++)
#pragma unroll
            for (int r = 0; r < 4; r++)
                f[r][o] = Lb[(size_t)o * PN + r * 128];
#pragma unroll
        for (int r = 0; r < 4; r++) {
            float m = f[r][0];
#pragma unroll
            for (int o = 1; o < 9; o++) m = fmaxf(m, f[r][o]);
            float s = 0.f;
#pragma unroll
            for (int o = 0; o < 9; o++) {
                float e = __expf(f[r][o] - m);
                f[r][o] = e;
                s += e;
            }
            const float rcp = 1.f / s;
#pragma unroll
            for (int o = 0; o < 9; o++) f[r][o] *= rcp;
        }
    }

    float* dstb = g_cat + ((size_t)n * 640 + (size_t)slot * 128) * PN
                + (size_t)(py0 + by) * 128 + px0 + tx;

    CPA_WAIT0();
    __syncthreads();

    for (int c = 0; c < 128; c++) {
        const int cur = c & 1;
        if (c < 127) { stage(cur ^ 1, c + 1); CPA_COMMIT(); }

        const float* tl = &tile[cur][0];
        float o_[4];
#pragma unroll
        for (int r = 0; r < 4; r++) o_[r] = 0.f;
#pragma unroll
        for (int i = 0; i < 3; i++)
#pragma unroll
            for (int j = 0; j < 3; j++) {
                const int k = i * 3 + j;
                const int col = tx + 16 + (j - 1) * d;
#pragma unroll
                for (int r = 0; r < 4; r++)
                    o_[r] = fmaf(tl[(by + r + i * d) * T_STR + col],
                                 f[r][k], o_[r]);
            }

        float* dst = dstb + (size_t)c * PN;
#pragma unroll
        for (int r = 0; r < 4; r++) dst[r * 128] = o_[r];

        if (c < 127) CPA_WAIT0();
        __syncthreads();
    }
}

// ---------------------------------------------------------------------------
extern "C" void kernel_launch(void* const* d_in, const int* in_sizes, int n_in,
                              void* d_out, int out_size)
{
    const float* x   = (const float*)d_in[0];
    const float* w1  = (const float*)d_in[1];
    const float* g1g = (const float*)d_in[2];
    const float* g1b = (const float*)d_in[3];
    const float* wca = (const float*)d_in[4];
    const float* wcb = (const float*)d_in[5];
    const float* wcc = (const float*)d_in[6];
    const float* wcd = (const float*)d_in[7];
    const float* w2  = (const float*)d_in[8];
    const float* g2g = (const float*)d_in[9];
    const float* g2b = (const float*)d_in[10];
    const float* w3  = (const float*)d_in[11];
    const float* g3g = (const float*)d_in[12];
    const float* g3b = (const float*)d_in[13];
    float* out = (float*)d_out;

    float *pre, *cat, *y2;
    cudaGetSymbolAddress((void**)&pre, g_pre);
    cudaGetSymbolAddress((void**)&cat, g_cat);
    cudaGetSymbolAddress((void**)&y2,  g_y2);

    cudaFuncSetAttribute(gemm_tf32_kernel,
                         cudaFuncAttributeMaxDynamicSharedMemorySize, GEMM_SMEM);

    // scale1: 1x1 conv (512->128) -> GN -> ReLU (into cat channels [0,128))
    gemm_tf32_kernel<<<dim3(128, 1, 4), 256, GEMM_SMEM>>>(w1, x, pre, 128, 512);
    gn_stats_kernel<<<dim3(32, 4, 8), 256>>>(pre, 128, 4);
    gn_apply_kernel<<<dim3(32, 4, 8), 256>>>(pre, cat, g1g, g1b, 128, 640, 0, 4);

    // dyn-filter branches: tensor-core logits, then softmax+gather
    dyn_logits_kernel<<<dim3(128, 16), 128>>>(wca, wcb, wcc, wcd);
    branch_apply_kernel<<<dim3(4, 4, 16), 256>>>();

    // scale2: 1x1 conv (640->128) -> GN -> ReLU
    gemm_tf32_kernel<<<dim3(128, 1, 4), 256, GEMM_SMEM>>>(w2, cat, pre, 128, 640);
    gn_stats_kernel<<<dim3(32, 4, 8), 256>>>(pre, 128, 4);
    gn_apply_kernel<<<dim3(32, 4, 8), 256>>>(pre, y2, g2g, g2b, 128, 128, 0, 4);

    // scale3: 1x1 conv (128->512) -> GN -> ReLU -> d_out
    gemm_tf32_kernel<<<dim3(128, 4, 4), 256, GEMM_SMEM>>>(w3, y2, pre, 512, 128);
    gn_stats_kernel<<<dim3(32, 4, 8), 256>>>(pre, 512, 16);
    gn_apply_kernel<<<dim3(32, 4, 8), 256>>>(pre, out, g3g, g3b, 512, 512, 0, 16);
}